// round 1
// baseline (speedup 1.0000x reference)
#include <cuda_runtime.h>

#define T_STEPS 100
#define BATCH   256
#define D0      784
#define D1      1024
#define D2      256
#define XWORDS  25     // ceil(784/32)
#define S1WORDS 32     // 1024/32

// LIF constants, matched to f32 rounding of the python doubles:
// ALPHA = f32(1 - 1e-3/5e-3) = 0.8f
// BETA  = f32(1 - 1e-3/2e-2) = 0.95f
// (1-BETA) computed in double then cast = 0.05f  (NOT 1.0f-0.95f in f32!)
#define ALPHA 0.8f
#define BETA  0.95f
#define OMB   0.05f

// ---------------- device scratch (no allocations allowed) ----------------
__device__ float    g_Wt1[D0 * D1];          // W1 transposed: [k][j], contiguous j
__device__ float    g_Wt2[D1 * D2];          // W2 transposed
__device__ float    g_I1[BATCH * D1];
__device__ float    g_V1[BATCH * D1];
__device__ float    g_I2[BATCH * D2];
__device__ float    g_V2[BATCH * D2];
__device__ unsigned g_xmask[T_STEPS * BATCH * XWORDS];   // packed input spikes
__device__ unsigned g_s1mask[2 * BATCH * S1WORDS];       // double-buffered layer-1 spikes

// ---------------- prep kernels ----------------
__global__ void transpose_W1(const float* __restrict__ W1) {
    int idx = blockIdx.x * blockDim.x + threadIdx.x;     // over D0*D1, idx = k*D1 + j
    if (idx < D0 * D1) {
        int k = idx / D1, j = idx % D1;
        g_Wt1[idx] = W1[j * D0 + k];
    }
}

__global__ void transpose_W2(const float* __restrict__ W2) {
    int idx = blockIdx.x * blockDim.x + threadIdx.x;     // over D1*D2, idx = k*D2 + j
    if (idx < D1 * D2) {
        int k = idx / D2, j = idx % D2;
        g_Wt2[idx] = W2[j * D1 + k];
    }
}

// one block per (t,b) row; 800 threads = 25 full warps; warp w builds word w
__global__ void pack_x(const float* __restrict__ x) {
    int row  = blockIdx.x;               // 0 .. T*BATCH-1
    int i    = threadIdx.x;              // 0 .. 799
    int lane = i & 31, w = i >> 5;
    bool p = (i < D0) && (x[(size_t)row * D0 + i] != 0.0f);
    unsigned m = __ballot_sync(0xffffffffu, p);
    if (lane == 0) g_xmask[row * XWORDS + w] = m;
}

__global__ void init_state(float* __restrict__ out) {
    int i = blockIdx.x * blockDim.x + threadIdx.x;
    if (i < BATCH * D1) { g_I1[i] = 0.f; g_V1[i] = 0.f; }
    if (i < BATCH * D2) { g_I2[i] = 0.f; g_V2[i] = 0.f; out[i] = 0.f; }  // out slice t=0
    if (i < 2 * BATCH * S1WORDS) g_s1mask[i] = 0u;
}

// ---------------- fused per-timestep kernel ----------------
// blocks [0, BATCH):        layer 1, one batch row each, 1024 threads = 1024 neurons
// blocks [BATCH, BATCH+64): layer 2, 4 batch rows each (256 threads per row)
__global__ void __launch_bounds__(1024, 2)
step_kernel(float* __restrict__ out, int t) {
    __shared__ unsigned sh[4 * S1WORDS];
    int bx = blockIdx.x;

    if (bx < BATCH) {
        // ---- layer 1: I1 = a*I1 + sum of active W1 columns; spike -> bitmask ----
        int b = bx, j = threadIdx.x;
        if (j < XWORDS) sh[j] = g_xmask[((t - 1) * BATCH + b) * XWORDS + j];
        __syncthreads();

        float acc = 0.f;
        #pragma unroll 1
        for (int w = 0; w < XWORDS; ++w) {
            unsigned bits = sh[w];
            const float* base = g_Wt1 + (w << 5) * D1 + j;
            while (bits) {
                int bb = __ffs(bits) - 1;
                bits &= bits - 1;
                acc += base[bb * D1];          // deterministic ascending-k order
            }
        }

        int idx = b * D1 + j;
        float I  = ALPHA * g_I1[idx] + acc;
        float Vp = BETA * g_V1[idx] + OMB * I;
        bool  s  = Vp > 1.0f;
        g_I1[idx] = I;
        g_V1[idx] = s ? 0.f : Vp;

        unsigned m = __ballot_sync(0xffffffffu, s);
        if ((j & 31) == 0)
            g_s1mask[(t & 1) * (BATCH * S1WORDS) + b * S1WORDS + (j >> 5)] = m;
    } else {
        // ---- layer 2: reads s1[t-1] bitmask, writes s2[t] to out ----
        int g = threadIdx.x >> 8;                  // 0..3 sub-groups
        int b = (bx - BATCH) * 4 + g;
        int j = threadIdx.x & 255;
        unsigned* shg = sh + g * S1WORDS;
        if (j < S1WORDS)
            shg[j] = g_s1mask[((t - 1) & 1) * (BATCH * S1WORDS) + b * S1WORDS + j];
        __syncthreads();

        float acc = 0.f;
        #pragma unroll 1
        for (int w = 0; w < S1WORDS; ++w) {
            unsigned bits = shg[w];
            const float* base = g_Wt2 + (w << 5) * D2 + j;
            while (bits) {
                int bb = __ffs(bits) - 1;
                bits &= bits - 1;
                acc += base[bb * D2];
            }
        }

        int idx = b * D2 + j;
        float I  = ALPHA * g_I2[idx] + acc;
        float Vp = BETA * g_V2[idx] + OMB * I;
        bool  s  = Vp > 1.0f;
        g_I2[idx] = I;
        g_V2[idx] = s ? 0.f : Vp;
        out[t * (BATCH * D2) + idx] = s ? 1.0f : 0.0f;
    }
}

// ---------------- launch ----------------
extern "C" void kernel_launch(void* const* d_in, const int* in_sizes, int n_in,
                              void* d_out, int out_size) {
    // pick inputs by element count (robust to metadata ordering)
    const float *x = nullptr, *W1 = nullptr, *W2 = nullptr;
    for (int i = 0; i < n_in; ++i) {
        if      (in_sizes[i] == T_STEPS * BATCH * D0) x  = (const float*)d_in[i];
        else if (in_sizes[i] == D1 * D0)              W1 = (const float*)d_in[i];
        else if (in_sizes[i] == D2 * D1)              W2 = (const float*)d_in[i];
    }
    float* out = (float*)d_out;

    transpose_W1<<<(D0 * D1 + 255) / 256, 256>>>(W1);
    transpose_W2<<<(D1 * D2 + 255) / 256, 256>>>(W2);
    pack_x<<<T_STEPS * BATCH, 800>>>(x);
    init_state<<<(BATCH * D1 + 255) / 256, 256>>>(out);

    for (int t = 1; t < T_STEPS; ++t)
        step_kernel<<<BATCH + BATCH / 4, 1024>>>(out, t);
}

// round 4
// speedup vs baseline: 2.0568x; 2.0568x over previous
#include <cuda_runtime.h>

#define T_STEPS 100
#define BATCH   256
#define D0      784
#define D1      1024
#define D2      256
#define XCAP    128

#define ALPHA 0.8f
#define BETA  0.95f
#define OMB   0.05f

#define NB_L1 128              // 2 batch rows each, 256 threads per row
#define NB_L2 32               // 8 batch rows each, 64 threads per row
#define NBLOCKS (NB_L1 + NB_L2)
#define NTHREADS 512

// ---------------- device scratch ----------------
__device__ float g_Wt1[(D0 + 1) * D1];                 // transposed, row D0 = zeros (pad)
__device__ float g_Wt2[(D1 + 1) * D2];                 // transposed, row D1 = zeros (pad)
__device__ unsigned short g_xidx[T_STEPS * BATCH * XCAP];
__device__ int g_xnnz[T_STEPS * BATCH];                // padded-to-4 counts
__device__ unsigned short g_s1idx[2][BATCH][D1];       // double-buffered layer-1 spike lists
__device__ int g_s1nnz[2][BATCH];
__device__ unsigned g_count;
__device__ volatile unsigned g_gen;

// ---------------- prep kernels ----------------
__global__ void transpose_W1(const float* __restrict__ W1) {
    int idx = blockIdx.x * blockDim.x + threadIdx.x;
    if (idx < (D0 + 1) * D1) {
        int k = idx / D1, j = idx % D1;
        g_Wt1[idx] = (k < D0) ? W1[j * D0 + k] : 0.0f;
    }
}

__global__ void transpose_W2(const float* __restrict__ W2) {
    int idx = blockIdx.x * blockDim.x + threadIdx.x;
    if (idx < (D1 + 1) * D2) {
        int k = idx / D2, j = idx % D2;
        g_Wt2[idx] = (k < D1) ? W2[j * D1 + k] : 0.0f;
    }
}

// one warp per (t,b) row; ascending index compaction (deterministic order)
__global__ void build_xidx(const float* __restrict__ x) {
    int row  = blockIdx.x * 8 + (threadIdx.x >> 5);
    int lane = threadIdx.x & 31;
    const float* xr = x + (size_t)row * D0;
    unsigned short* out = g_xidx + row * XCAP;
    int base = 0;
    #pragma unroll 1
    for (int c = 0; c < 25; ++c) {
        int i = c * 32 + lane;
        bool p = (i < D0) && (xr[i] != 0.0f);
        unsigned m = __ballot_sync(0xffffffffu, p);
        if (p) out[base + __popc(m & ((1u << lane) - 1u))] = (unsigned short)i;
        base += __popc(m);
    }
    if (lane == 0) {
        int nnzp = (base + 3) & ~3;            // pad to multiple of 4 with zero-row index
        for (int p = base; p < nnzp; ++p) out[p] = (unsigned short)D0;
        g_xnnz[row] = nnzp;
    }
}

__global__ void init_misc(float* __restrict__ out) {
    int i = blockIdx.x * blockDim.x + threadIdx.x;
    if (i < BATCH * D2) out[i] = 0.0f;         // spikes[t=0] = 0
    if (i < BATCH) g_s1nnz[0][i] = 0;          // s1[t=0] empty
    if (i == 0) { g_count = 0; g_gen = 0; }
}

// ---------------- grid barrier (all NBLOCKS blocks co-resident) ----------------
__device__ __forceinline__ void grid_barrier(unsigned target) {
    __threadfence();
    __syncthreads();
    if (threadIdx.x == 0) {
        unsigned t = atomicAdd(&g_count, 1u);
        if (t == NBLOCKS - 1) {
            g_count = 0;
            __threadfence();
            g_gen = target;
        } else {
            while (g_gen < target) { }
            __threadfence();
        }
    }
    __syncthreads();
}

// ---------------- persistent SNN kernel ----------------
__global__ void __launch_bounds__(NTHREADS, 2)
snn_persistent(float* __restrict__ out) {
    __shared__ __align__(16) unsigned short sh16[8 * 1024];  // 16 KB: L2 idx staging / L1 idx staging
    __shared__ int shw[16];                                  // per-warp spike-count totals (layer 1)

    int bx = blockIdx.x;
    unsigned tid = threadIdx.x;

    if (bx < NB_L1) {
        // ================= layer 1: 2 rows/block, 256 threads per row (float4 over D1) =================
        int rl   = tid >> 8;                    // 0..1
        int j    = tid & 255;                   // neuron group: 4j..4j+3
        int row  = bx * 2 + rl;
        int warp = tid >> 5;                    // 0..15
        int lane = tid & 31;
        int wlo  = rl * 8;                      // first warp of this row
        const float4* W = (const float4*)g_Wt1; // row k: W[k*256 + j]
        unsigned short* shx = sh16 + rl * XCAP;
        float4 I = make_float4(0.f, 0.f, 0.f, 0.f);
        float4 V = make_float4(0.f, 0.f, 0.f, 0.f);

        for (int t = 1; t < T_STEPS; ++t) {
            int xr   = (t - 1) * BATCH + row;
            int nnzp = g_xnnz[xr];
            if (j < nnzp) shx[j] = g_xidx[xr * XCAP + j];
            __syncthreads();

            float4 acc = make_float4(0.f, 0.f, 0.f, 0.f);
            #pragma unroll 1
            for (int i = 0; i < nnzp; i += 4) {
                ushort4 kk = *(const ushort4*)(shx + i);
                float4 a = W[(int)kk.x * 256 + j];
                float4 b = W[(int)kk.y * 256 + j];
                float4 c = W[(int)kk.z * 256 + j];
                float4 d = W[(int)kk.w * 256 + j];
                acc.x += a.x; acc.y += a.y; acc.z += a.z; acc.w += a.w;
                acc.x += b.x; acc.y += b.y; acc.z += b.z; acc.w += b.w;
                acc.x += c.x; acc.y += c.y; acc.z += c.z; acc.w += c.w;
                acc.x += d.x; acc.y += d.y; acc.z += d.z; acc.w += d.w;
            }

            I.x = ALPHA * I.x + acc.x;  I.y = ALPHA * I.y + acc.y;
            I.z = ALPHA * I.z + acc.z;  I.w = ALPHA * I.w + acc.w;
            float4 Vp;
            Vp.x = BETA * V.x + OMB * I.x;  Vp.y = BETA * V.y + OMB * I.y;
            Vp.z = BETA * V.z + OMB * I.z;  Vp.w = BETA * V.w + OMB * I.w;
            bool s0 = Vp.x > 1.0f, s1 = Vp.y > 1.0f, s2 = Vp.z > 1.0f, s3 = Vp.w > 1.0f;
            V.x = s0 ? 0.f : Vp.x;  V.y = s1 ? 0.f : Vp.y;
            V.z = s2 ? 0.f : Vp.z;  V.w = s3 ? 0.f : Vp.w;

            // build ascending spike index list for this row
            int nib = (int)s0 | ((int)s1 << 1) | ((int)s2 << 2) | ((int)s3 << 3);
            int cnt = __popc((unsigned)nib);
            int incl = cnt;
            #pragma unroll
            for (int o = 1; o < 32; o <<= 1) {
                int v = __shfl_up_sync(0xffffffffu, incl, o);
                if (lane >= o) incl += v;
            }
            if (lane == 31) shw[warp] = incl;
            __syncthreads();
            int basew = 0;
            for (int w = wlo; w < warp; ++w) basew += shw[w];
            int off = basew + incl - cnt;
            int buf = t & 1;
            unsigned short* dst = &g_s1idx[buf][row][0];
            int jj = j << 2;
            if (s0) dst[off++] = (unsigned short)(jj + 0);
            if (s1) dst[off++] = (unsigned short)(jj + 1);
            if (s2) dst[off++] = (unsigned short)(jj + 2);
            if (s3) dst[off++] = (unsigned short)(jj + 3);
            if (j == 255) {
                int nnz = basew + incl;
                int nnzp2 = (nnz + 3) & ~3;
                for (int p = nnz; p < nnzp2; ++p) dst[p] = (unsigned short)D1;
                g_s1nnz[buf][row] = nnzp2;
            }

            if (t < T_STEPS - 1) grid_barrier((unsigned)t);
        }
    } else {
        // ================= layer 2: 8 rows/block, 64 threads per row (float4 over D2) =================
        int b2  = bx - NB_L1;                   // 0..31
        int rl  = tid >> 6;                     // 0..7
        int j   = tid & 63;                     // neuron group: 4j..4j+3
        int row = b2 * 8 + rl;
        const float4* W = (const float4*)g_Wt2; // row k: W[k*64 + j]
        unsigned short* shr = sh16 + rl * 1024;
        float4 I = make_float4(0.f, 0.f, 0.f, 0.f);
        float4 V = make_float4(0.f, 0.f, 0.f, 0.f);
        float4* out4 = (float4*)out;

        for (int t = 1; t < T_STEPS; ++t) {
            int buf  = (t - 1) & 1;
            int nnzp = __ldcg(&g_s1nnz[buf][row]);
            for (int i = j; i < nnzp; i += 64)
                shr[i] = __ldcg(&g_s1idx[buf][row][i]);
            __syncthreads();

            float4 acc = make_float4(0.f, 0.f, 0.f, 0.f);
            #pragma unroll 1
            for (int i = 0; i < nnzp; i += 4) {
                ushort4 kk = *(const ushort4*)(shr + i);
                float4 a = W[(int)kk.x * 64 + j];
                float4 b = W[(int)kk.y * 64 + j];
                float4 c = W[(int)kk.z * 64 + j];
                float4 d = W[(int)kk.w * 64 + j];
                acc.x += a.x; acc.y += a.y; acc.z += a.z; acc.w += a.w;
                acc.x += b.x; acc.y += b.y; acc.z += b.z; acc.w += b.w;
                acc.x += c.x; acc.y += c.y; acc.z += c.z; acc.w += c.w;
                acc.x += d.x; acc.y += d.y; acc.z += d.z; acc.w += d.w;
            }

            I.x = ALPHA * I.x + acc.x;  I.y = ALPHA * I.y + acc.y;
            I.z = ALPHA * I.z + acc.z;  I.w = ALPHA * I.w + acc.w;
            float4 Vp;
            Vp.x = BETA * V.x + OMB * I.x;  Vp.y = BETA * V.y + OMB * I.y;
            Vp.z = BETA * V.z + OMB * I.z;  Vp.w = BETA * V.w + OMB * I.w;
            bool s0 = Vp.x > 1.0f, s1 = Vp.y > 1.0f, s2 = Vp.z > 1.0f, s3 = Vp.w > 1.0f;
            V.x = s0 ? 0.f : Vp.x;  V.y = s1 ? 0.f : Vp.y;
            V.z = s2 ? 0.f : Vp.z;  V.w = s3 ? 0.f : Vp.w;

            float4 o = make_float4(s0 ? 1.f : 0.f, s1 ? 1.f : 0.f,
                                   s2 ? 1.f : 0.f, s3 ? 1.f : 0.f);
            out4[(t * BATCH * D2 + row * D2) / 4 + j] = o;

            if (t < T_STEPS - 1) grid_barrier((unsigned)t);
        }
    }
}

// ---------------- launch ----------------
extern "C" void kernel_launch(void* const* d_in, const int* in_sizes, int n_in,
                              void* d_out, int out_size) {
    const float *x = nullptr, *W1 = nullptr, *W2 = nullptr;
    for (int i = 0; i < n_in; ++i) {
        if      (in_sizes[i] == T_STEPS * BATCH * D0) x  = (const float*)d_in[i];
        else if (in_sizes[i] == D1 * D0)              W1 = (const float*)d_in[i];
        else if (in_sizes[i] == D2 * D1)              W2 = (const float*)d_in[i];
    }
    float* out = (float*)d_out;

    transpose_W1<<<((D0 + 1) * D1 + 255) / 256, 256>>>(W1);
    transpose_W2<<<((D1 + 1) * D2 + 255) / 256, 256>>>(W2);
    build_xidx<<<T_STEPS * BATCH / 8, 256>>>(x);
    init_misc<<<(BATCH * D2 + 255) / 256, 256>>>(out);
    snn_persistent<<<NBLOCKS, NTHREADS>>>(out);
}